// round 8
// baseline (speedup 1.0000x reference)
#include <cuda_runtime.h>

#define BB 2
#define NN 40000
#define MM 40000
#define PP 128
#define KK 32
#define KC 4
#define FD 128
#define GG 32
#define NCELLS (GG*GG*GG)
#define HH (1.0f/GG)
#define CAPC 16              /* slots per cell */
#define CAP32 2048
#define FINF 3.402823466e38f

// ---------------- device scratch (no allocations allowed) ----------------
__device__ int    g_cntN[BB*NCELLS];
__device__ int    g_cntC[BB*NCELLS];
__device__ float4 g_slotN[BB*NCELLS*CAPC];
__device__ float4 g_slotC[BB*NCELLS*CAPC];
__device__ unsigned long long g_acc;
__device__ unsigned int g_done;

__device__ __forceinline__ int cell_of(float x, float y, float z) {
    int cx = min(max((int)(x * GG), 0), GG-1);
    int cy = min(max((int)(y * GG), 0), GG-1);
    int cz = min(max((int)(z * GG), 0), GG-1);
    return (cz*GG + cy)*GG + cx;
}

// ---------------- zero counters + accumulators (vectorized) ----------------
__global__ void zero_kernel() {
    int i = blockIdx.x * blockDim.x + threadIdx.x;
    int4* a = reinterpret_cast<int4*>(g_cntN);
    int4* c = reinterpret_cast<int4*>(g_cntC);
    int n4 = (BB*NCELLS) / 4;
    int4 z = make_int4(0, 0, 0, 0);
    for (; i < n4; i += gridDim.x * blockDim.x) { a[i] = z; c[i] = z; }
    if (blockIdx.x == 0 && threadIdx.x == 0) { g_acc = 0ULL; g_done = 0u; }
}

// ---------------- insert points into cell slots ----------------
__global__ void insert_kernel(const float* __restrict__ noisy,
                              const float* __restrict__ clean) {
    int i = blockIdx.x * blockDim.x + threadIdx.x;
    if (i >= BB*NN) return;
    int b = i / NN;
    {
        float x = noisy[3*i], y = noisy[3*i+1], z = noisy[3*i+2];
        int c = b*NCELLS + cell_of(x, y, z);
        int pos = atomicAdd(&g_cntN[c], 1);
        if (pos < CAPC) g_slotN[c*CAPC + pos] = make_float4(x, y, z, 0.f);
    }
    {
        float x = clean[3*i], y = clean[3*i+1], z = clean[3*i+2];
        int c = b*NCELLS + cell_of(x, y, z);
        int pos = atomicAdd(&g_cntC[c], 1);
        if (pos < CAPC) g_slotC[c*CAPC + pos] = make_float4(x, y, z, 0.f);
    }
}

// 4-NN insert tracking distances AND coordinates (no index -> no gather later)
#define INS4C(VAL, X, Y, Z)                                                   \
    do {                                                                      \
        if ((VAL) < d3) {                                                     \
            if ((VAL) < d2) {                                                 \
                d3 = d2; x3 = x2; y3 = y2; z3 = z2;                           \
                if ((VAL) < d1) {                                             \
                    d2 = d1; x2 = x1; y2 = y1; z2 = z1;                       \
                    if ((VAL) < d0) {                                         \
                        d1 = d0; x1 = x0; y1 = y0; z1 = z0;                   \
                        d0 = (VAL); x0 = (X); y0 = (Y); z0 = (Z);             \
                    } else { d1 = (VAL); x1 = (X); y1 = (Y); z1 = (Z); }      \
                } else { d2 = (VAL); x2 = (X); y2 = (Y); z2 = (Z); }          \
            } else { d3 = (VAL); x3 = (X); y3 = (Y); z3 = (Z); }              \
        }                                                                     \
    } while (0)

// ---------------- fused main kernel: one 1024-thread CTA per first-stage query ----------------
__global__ __launch_bounds__(1024) void main_kernel(
        const float* __restrict__ noisy,
        const int*   __restrict__ sidx,
        const float* __restrict__ Wf,
        const float* __restrict__ Wx,
        const float* __restrict__ Wc,
        float* __restrict__ out) {
    __shared__ float bd[CAP32];
    __shared__ int   bi[CAP32];
    __shared__ int   sh_cnt, sh_lt;
    __shared__ float sfx[KK], sfy[KK], sfz[KK];
    __shared__ float sc[3];
    __shared__ unsigned long long sh_acc;
    int tid = threadIdx.x, lane = tid & 31, warp = tid >> 5;
    int qid = blockIdx.x;                  // 0..255
    int b = qid >> 7, p = qid & 127;

    int gi = b*NN + sidx[p];
    float qx = noisy[3*gi], qy = noisy[3*gi+1], qz = noisy[3*gi+2];
    if (tid == 0) { sh_cnt = 0; sh_lt = 0; sh_acc = 0ULL; }

    // ---- phase 0: warp 1 computes c = (q@Wf)@Wc ----
    if (warp == 1) {
        float a0 = 0.f, a1 = 0.f, a2 = 0.f;
        #pragma unroll
        for (int u = 0; u < 4; u++) {
            int f = lane + 32*u;
            float ft = qx*Wf[f] + qy*Wf[FD+f] + qz*Wf[2*FD+f];
            a0 += ft * Wc[3*f+0];
            a1 += ft * Wc[3*f+1];
            a2 += ft * Wc[3*f+2];
        }
        for (int off = 16; off; off >>= 1) {
            a0 += __shfl_xor_sync(0xffffffffu, a0, off);
            a1 += __shfl_xor_sync(0xffffffffu, a1, off);
            a2 += __shfl_xor_sync(0xffffffffu, a2, off);
        }
        if (lane == 0) { sc[0] = a0; sc[1] = a1; sc[2] = a2; }
    }
    __syncthreads();

    // ---- phase 1: KNN-32 over noisy grid (CTA-wide collect + count) ----
    int qcx = min(max((int)(qx * GG), 0), GG-1);
    int qcy = min(max((int)(qy * GG), 0), GG-1);
    int qcz = min(max((int)(qz * GG), 0), GG-1);
    const int*    ncnt  = g_cntN  + b*NCELLS;
    const float4* nslot = g_slotN + (long)b*NCELLS*CAPC;

    int r = 2;
    {
        int side = 5, n = side*side*side;           // rings 0..2: 125 cells
        for (int t = tid; t < n; t += 1024) {
            int dz = t/(side*side) - 2, rem = t%(side*side);
            int dy = rem/side - 2, dx = rem%side - 2;
            int cx = qcx+dx, cy = qcy+dy, cz = qcz+dz;
            if (cx < 0 || cx >= GG || cy < 0 || cy >= GG || cz < 0 || cz >= GG) continue;
            int c = (cz*GG + cy)*GG + cx;
            int e = min(ncnt[c], CAPC);
            int base = c*CAPC;
            for (int j = 0; j < e; j++) {
                float4 pt = nslot[base + j];
                float ddx = pt.x-qx, ddy = pt.y-qy, ddz = pt.z-qz;
                float d = fmaf(ddx, ddx, fmaf(ddy, ddy, ddz*ddz));
                int pos = atomicAdd(&sh_cnt, 1);
                if (pos < CAP32) { bd[pos] = d; bi[pos] = base + j; }
            }
        }
    }
    __syncthreads();

    while (true) {
        float T = (r*HH) * (r*HH);
        int n_in = min(sh_cnt, CAP32);
        int c = 0;
        for (int j = tid; j < n_in; j += 1024) if (bd[j] < T) c++;
        atomicAdd(&sh_lt, c);
        __syncthreads();
        int tot = sh_lt;
        __syncthreads();
        if (tid == 0) sh_lt = 0;
        if (tot >= KK || r >= 64) break;
        r++;
        int side = 2*r+1, n = side*side*side;
        for (int t = tid; t < n; t += 1024) {
            int dz = t/(side*side) - r, rem = t%(side*side);
            int dy = rem/side - r, dx = rem%side - r;
            if (max(abs(dx), max(abs(dy), abs(dz))) < r) continue;
            int cx = qcx+dx, cy = qcy+dy, cz = qcz+dz;
            if (cx < 0 || cx >= GG || cy < 0 || cy >= GG || cz < 0 || cz >= GG) continue;
            int cc = (cz*GG + cy)*GG + cx;
            int e = min(ncnt[cc], CAPC);
            int base = cc*CAPC;
            for (int j = 0; j < e; j++) {
                float4 pt = nslot[base + j];
                float ddx = pt.x-qx, ddy = pt.y-qy, ddz = pt.z-qz;
                float d = fmaf(ddx, ddx, fmaf(ddy, ddy, ddz*ddz));
                int pos = atomicAdd(&sh_cnt, 1);
                if (pos < CAP32) { bd[pos] = d; bi[pos] = base + j; }
            }
        }
        __syncthreads();
    }

    int total = min(sh_cnt, CAP32);
    if (warp == 0) {
        for (int rr = 0; rr < KK; rr++) {
            float mv = FINF; int mi = -1;
            for (int j = lane; j < total; j += 32) {
                float dv = bd[j];
                if (dv < mv) { mv = dv; mi = j; }
            }
            float v = mv; int src = lane;
            for (int off = 16; off; off >>= 1) {
                float vo = __shfl_xor_sync(0xffffffffu, v, off);
                int   so = __shfl_xor_sync(0xffffffffu, src, off);
                if (vo < v || (vo == v && so < src)) { v = vo; src = so; }
            }
            int slot = __shfl_sync(0xffffffffu, mi, src);
            if (lane == 0) {
                float4 pp = nslot[bi[slot]];
                sfx[rr] = pp.x; sfy[rr] = pp.y; sfz[rr] = pp.z;
            }
            if (lane == src) bd[slot] = FINF;
            __syncwarp();
        }
    }
    __syncthreads();

    // ---- phase 2: one warp per neighbor -> KNN-4 over clean grid + loss ----
    const int*    ccnt  = g_cntC  + b*NCELLS;
    const float4* cslot = g_slotC + (long)b*NCELLS*CAPC;

    {
        float fx = sfx[warp], fy = sfy[warp], fz = sfz[warp];
        int fcx = min(max((int)(fx * GG), 0), GG-1);
        int fcy = min(max((int)(fy * GG), 0), GG-1);
        int fcz = min(max((int)(fz * GG), 0), GG-1);

        float d0 = FINF, d1 = FINF, d2 = FINF, d3 = FINF;
        float x0=0.f,y0=0.f,z0=0.f, x1=0.f,y1=0.f,z1=0.f;
        float x2=0.f,y2=0.f,z2=0.f, x3=0.f,y3=0.f,z3=0.f;

        if (lane < 27) {                      // rings 0..1, one cell per lane
            int dz = lane/9 - 1, dy = (lane/3)%3 - 1, dx = lane%3 - 1;
            int cx = fcx+dx, cy = fcy+dy, cz = fcz+dz;
            if (cx >= 0 && cx < GG && cy >= 0 && cy < GG && cz >= 0 && cz < GG) {
                int c = (cz*GG + cy)*GG + cx;
                int e = min(ccnt[c], CAPC);
                int base = c*CAPC;
                for (int j = 0; j < e; j++) {
                    float4 pt = cslot[base + j];
                    float ddx = pt.x-fx, ddy = pt.y-fy, ddz = pt.z-fz;
                    float t = fmaf(ddx, ddx, fmaf(ddy, ddy, ddz*ddz));
                    INS4C(t, pt.x, pt.y, pt.z);
                }
            }
        }
        int rr = 1;
        while (true) {
            float T = (rr*HH) * (rr*HH);
            int c = (d0 < T) + (d1 < T) + (d2 < T) + (d3 < T);
            int tot = __reduce_add_sync(0xffffffffu, (unsigned)c);
            if (tot >= KC || rr >= 64) break;
            rr++;
            int side = 2*rr+1, n = side*side*side;
            for (int t = lane; t < n; t += 32) {
                int dz = t/(side*side) - rr, rem = t%(side*side);
                int dy = rem/side - rr, dx = rem%side - rr;
                if (max(abs(dx), max(abs(dy), abs(dz))) < rr) continue;
                int cx = fcx+dx, cy = fcy+dy, cz = fcz+dz;
                if (cx < 0 || cx >= GG || cy < 0 || cy >= GG || cz < 0 || cz >= GG) continue;
                int cc = (cz*GG + cy)*GG + cx;
                int e = min(ccnt[cc], CAPC);
                int base = cc*CAPC;
                for (int j = 0; j < e; j++) {
                    float4 pt = cslot[base + j];
                    float ddx = pt.x-fx, ddy = pt.y-fy, ddz = pt.z-fz;
                    float t2 = fmaf(ddx, ddx, fmaf(ddy, ddy, ddz*ddz));
                    INS4C(t2, pt.x, pt.y, pt.z);
                }
            }
        }

        // extract 4 global mins across lanes; coords come via shfl (no memory)
        float sx = 0.f, sy = 0.f, sz = 0.f;
        for (int e4 = 0; e4 < KC; e4++) {
            float v = d0; int src = lane;
            for (int off = 16; off; off >>= 1) {
                float vo = __shfl_xor_sync(0xffffffffu, v, off);
                int   so = __shfl_xor_sync(0xffffffffu, src, off);
                if (vo < v || (vo == v && so < src)) { v = vo; src = so; }
            }
            float wx_ = __shfl_sync(0xffffffffu, x0, src);
            float wy_ = __shfl_sync(0xffffffffu, y0, src);
            float wz_ = __shfl_sync(0xffffffffu, z0, src);
            if (lane == src) {
                d0 = d1; x0 = x1; y0 = y1; z0 = z1;
                d1 = d2; x1 = x2; y1 = y2; z1 = z2;
                d2 = d3; x2 = x3; y2 = y3; z2 = z3;
                d3 = FINF;
            }
            sx += wx_; sy += wy_; sz += wz_;
        }

        if (lane == 0) {
            float gx = 0.25f*sx - fx;
            float gy = 0.25f*sy - fy;
            float gz = 0.25f*sz - fz;
            float dx = fx - qx;
            float dy = fy - qy;
            float dz = fz - qz;
            float ex = sc[0] + dx*Wx[0] + dy*Wx[3] + dz*Wx[6];
            float ey = sc[1] + dx*Wx[1] + dy*Wx[4] + dz*Wx[7];
            float ez = sc[2] + dx*Wx[2] + dy*Wx[5] + dz*Wx[8];
            float r0 = ex - gx, r1 = ey - gy, r2 = ez - gz;
            float term = fmaf(r0, r0, fmaf(r1, r1, r2*r2));
            unsigned long long q =
                (unsigned long long)__double2ll_rn((double)term * 4294967296.0);
            atomicAdd(&sh_acc, q);
        }
    }
    __syncthreads();

    // ---- phase 3: one global atomic per CTA; last CTA writes the loss ----
    if (tid == 0) {
        atomicAdd(&g_acc, sh_acc);
        __threadfence();
        unsigned int old = atomicAdd(&g_done, 1u);
        if (old == gridDim.x - 1) {
            unsigned long long acc = atomicAdd(&g_acc, 0ULL);
            double sum = (double)acc * (1.0 / 4294967296.0);
            out[0] = (float)(sum * (0.5 / (0.01 * 8192.0)));
        }
    }
}

// ---------------- launch ----------------
extern "C" void kernel_launch(void* const* d_in, const int* in_sizes, int n_in,
                              void* d_out, int out_size) {
    const float* noisy = (const float*)d_in[0];
    const float* clean = (const float*)d_in[1];
    const int*   sidx  = (const int*)  d_in[2];
    const float* Wf    = (const float*)d_in[3];
    const float* Wx    = (const float*)d_in[4];
    const float* Wc    = (const float*)d_in[5];
    float* out = (float*)d_out;

    zero_kernel  <<<256, 256>>>();
    insert_kernel<<<(BB*NN + 255) / 256, 256>>>(noisy, clean);
    main_kernel  <<<BB*PP, 1024>>>(noisy, sidx, Wf, Wx, Wc, out);
}